// round 9
// baseline (speedup 1.0000x reference)
#include <cuda_runtime.h>
#include <cstdint>

// Problem constants (fixed by reference)
#define NB    8
#define HH    512
#define WW    512
#define DD    8
#define HWC   (HH * WW)          // 262144
#define NPIX  (NB * HWC)         // 2097152 = 2^21
#define PPT   8                  // contiguous pixels per thread
#define TPB   128
#define NTHREADS (NPIX / PPT)    // 262144
#define GRID  (NTHREADS / TPB)   // 2048

// ---- 256-bit accessors (sm_103: L2 eviction hints require v8.b32 / v4.b64) ----

// gather: 32 B, keep in L2 across replays
__device__ __forceinline__ void ldg256_el(const void* p, float4& a, float4& b) {
    asm volatile(
        "ld.global.nc.L2::evict_last.v8.b32 {%0,%1,%2,%3,%4,%5,%6,%7}, [%8];"
        : "=r"(*(unsigned*)&a.x), "=r"(*(unsigned*)&a.y),
          "=r"(*(unsigned*)&a.z), "=r"(*(unsigned*)&a.w),
          "=r"(*(unsigned*)&b.x), "=r"(*(unsigned*)&b.y),
          "=r"(*(unsigned*)&b.z), "=r"(*(unsigned*)&b.w)
        : "l"(p));
}
// single-use stream load: 32 B, evict first
__device__ __forceinline__ void ldg256_ef(const void* p, float* d) {
    asm volatile(
        "ld.global.nc.L2::evict_first.v8.b32 {%0,%1,%2,%3,%4,%5,%6,%7}, [%8];"
        : "=f"(d[0]), "=f"(d[1]), "=f"(d[2]), "=f"(d[3]),
          "=f"(d[4]), "=f"(d[5]), "=f"(d[6]), "=f"(d[7])
        : "l"(p));
}
__device__ __forceinline__ void ldg256_ef_i64(const void* p, long long* d) {
    asm volatile(
        "ld.global.nc.L2::evict_first.v4.b64 {%0,%1,%2,%3}, [%4];"
        : "=l"(d[0]), "=l"(d[1]), "=l"(d[2]), "=l"(d[3])
        : "l"(p));
}
// single-use stream store: 32 B, evict first
__device__ __forceinline__ void stg256_ef(void* p, const float* s) {
    asm volatile(
        "st.global.L2::evict_first.v8.b32 [%0], {%1,%2,%3,%4,%5,%6,%7,%8};"
        :: "l"(p),
           "f"(s[0]), "f"(s[1]), "f"(s[2]), "f"(s[3]),
           "f"(s[4]), "f"(s[5]), "f"(s[6]), "f"(s[7]));
}

__global__ __launch_bounds__(TPB)
void interp_kernel(const void* __restrict__ p2f_raw,
                   const float* __restrict__ bary,     // [NPIX,3]
                   const float* __restrict__ attr,     // [N*NF][3][8] fp32 = 96 B/face
                   float* __restrict__ out)            // [N][9][H][W]
{
    const int t    = blockIdx.x * TPB + threadIdx.x;   // t < 262144
    const int pix0 = t * PPT;                          // 8 consecutive pixels

    // ---- dtype detection (int64 vs int32 pix_to_face), warp-uniform ----
    // t < NPIX/2, so word 2t+1 is in-bounds under BOTH interpretations.
    // int64: hi word of every element is 0 or 0xFFFFFFFF -> 32/32 lanes match.
    // int32: sampled words are arbitrary face values -> ~6-7/32 match.
    const unsigned int* pw = (const unsigned int*)p2f_raw;
    unsigned int hiw = __ldg(&pw[2 * t + 1]);
    bool m = (hiw == 0u) || (hiw == 0xFFFFFFFFu);
    const bool is64 = __popc(__ballot_sync(0xffffffffu, m)) >= 28;

    // ---- stream loads: face indices (32/64 B) + barycentrics (96 B) ----
    int f[PPT];
    if (is64) {
        long long tmp[8];
        const char* base = (const char*)p2f_raw + (size_t)pix0 * 8;
        ldg256_ef_i64(base,      tmp);
        ldg256_ef_i64(base + 32, tmp + 4);
        #pragma unroll
        for (int p = 0; p < PPT; p++) f[p] = (int)tmp[p];   // faces < 8e5 fit int32
    } else {
        float tmp[8];
        ldg256_ef((const char*)p2f_raw + (size_t)pix0 * 4, tmp);
        #pragma unroll
        for (int p = 0; p < PPT; p++) f[p] = *(const int*)&tmp[p];
    }

    float b[24];                                       // 8 pixels x 3
    {
        const char* bp = (const char*)(bary + (size_t)pix0 * 3);
        ldg256_ef(bp,      b);
        ldg256_ef(bp + 32, b + 8);
        ldg256_ef(bp + 64, b + 16);
    }

    // ---- gather pipeline: 3 buffers, 2-pixel lookahead (6 LDG.256 in flight) ----
    float4 A[3][6];
    auto load_attr = [&](int buf, int p) {
        if (f[p] >= 0) {
            const float* a = attr + (size_t)f[p] * 24;
            ldg256_el(a + 0,  A[buf][0], A[buf][1]);   // vertex 0: ch 0-7
            ldg256_el(a + 8,  A[buf][2], A[buf][3]);   // vertex 1
            ldg256_el(a + 16, A[buf][4], A[buf][5]);   // vertex 2
        }
    };

    float o[DD + 1][PPT];                              // plane-major accumulate

    load_attr(0, 0);
    load_attr(1, 1);

    #pragma unroll
    for (int p = 0; p < PPT; p++) {
        if (p + 2 < PPT) load_attr((p + 2) % 3, p + 2);

        const int buf = p % 3;
        if (f[p] >= 0) {
            float b0 = b[p * 3 + 0], b1 = b[p * 3 + 1], b2 = b[p * 3 + 2];
            float4 A0 = A[buf][0], A1 = A[buf][1];
            float4 A2 = A[buf][2], A3 = A[buf][3];
            float4 A4 = A[buf][4], A5 = A[buf][5];
            o[0][p] = b0 * A0.x + b1 * A2.x + b2 * A4.x;
            o[1][p] = b0 * A0.y + b1 * A2.y + b2 * A4.y;
            o[2][p] = b0 * A0.z + b1 * A2.z + b2 * A4.z;
            o[3][p] = b0 * A0.w + b1 * A2.w + b2 * A4.w;
            o[4][p] = b0 * A1.x + b1 * A3.x + b2 * A5.x;
            o[5][p] = b0 * A1.y + b1 * A3.y + b2 * A5.y;
            o[6][p] = b0 * A1.z + b1 * A3.z + b2 * A5.z;
            o[7][p] = b0 * A1.w + b1 * A3.w + b2 * A5.w;
            o[8][p] = 1.0f;
        } else {
            #pragma unroll
            for (int d = 0; d <= DD; d++) o[d][p] = 0.0f;
        }
    }

    // ---- output [N][9][H][W]: 9 x 256-bit evict-first stores ----
    int n  = pix0 >> 18;                               // / HWC (2^18)
    int hw = pix0 & (HWC - 1);                         // multiple of 8 -> 32 B aligned
    float* ob = out + (size_t)n * (DD + 1) * HWC + hw;
    #pragma unroll
    for (int d = 0; d <= DD; d++)
        stg256_ef(ob + (size_t)d * HWC, o[d]);
}

extern "C" void kernel_launch(void* const* d_in, const int* in_sizes, int n_in,
                              void* d_out, int out_size) {
    const void*  p2f  = d_in[0];                    // [N,H,W,1] int32 or int64
    const float* bary = (const float*)d_in[1];      // [N,H,W,1,3] fp32
    const float* attr = (const float*)d_in[2];      // [N,NF,3,8] fp32
    float*       out  = (float*)d_out;              // [N,9,H,W] fp32

    interp_kernel<<<GRID, TPB>>>(p2f, bary, attr, out);
}

// round 10
// speedup vs baseline: 1.2375x; 1.2375x over previous
#include <cuda_runtime.h>
#include <cstdint>

// Problem constants (fixed by reference)
#define NB    8
#define HH    512
#define WW    512
#define DD    8
#define HWC   (HH * WW)          // 262144
#define NPIX  (NB * HWC)         // 2097152 = 2^21
#define TPB   128
#define GRID  2048
#define TOTAL (GRID * TPB)       // 262144 threads
#define ITERS (NPIX / TOTAL)     // 8 pixels per thread, exact

// 256-bit gather load with L2 evict_last (sm_103 requires v8.b32 for this hint).
__device__ __forceinline__ void ldg256_el(const void* p, float4& a, float4& b) {
    asm volatile(
        "ld.global.nc.L2::evict_last.v8.b32 {%0,%1,%2,%3,%4,%5,%6,%7}, [%8];"
        : "=r"(*(unsigned*)&a.x), "=r"(*(unsigned*)&a.y),
          "=r"(*(unsigned*)&a.z), "=r"(*(unsigned*)&a.w),
          "=r"(*(unsigned*)&b.x), "=r"(*(unsigned*)&b.y),
          "=r"(*(unsigned*)&b.z), "=r"(*(unsigned*)&b.w)
        : "l"(p));
}

__global__ __launch_bounds__(TPB, 6)
void interp_kernel(const void* __restrict__ p2f_raw,
                   const float* __restrict__ bary,     // [NPIX,3]
                   const float* __restrict__ attr,     // [N*NF][3][8] fp32 = 96 B/face
                   float* __restrict__ out)            // [N][9][H][W]
{
    const int t = blockIdx.x * TPB + threadIdx.x;      // base pixel (t < NPIX/8)

    // ---- dtype detection (int64 vs int32 pix_to_face), warp-uniform ----
    // t < NPIX/2, so word index 2t+1 is in-bounds under BOTH interpretations.
    // int64: hi word of every element is 0 or 0xFFFFFFFF -> 32/32 lanes match.
    // int32: sampled words are arbitrary face values -> ~6-7/32 match.
    const unsigned int* pw = (const unsigned int*)p2f_raw;
    unsigned int hiw = __ldg(&pw[2 * t + 1]);
    bool m = (hiw == 0u) || (hiw == 0xFFFFFFFFu);
    const bool is64 = __popc(__ballot_sync(0xffffffffu, m)) >= 28;

    // Pipeline state: 3 idx/bary slots, 2 attr buffers.
    int    fq[3];
    float  bq[3][3];
    float4 A[2][6];

    // issue face index + barycentrics for stage j into slot s (single-use -> evict-first)
    auto load_idx = [&](int s, int j) {
        int pix = t + j * TOTAL;
        if (is64) fq[s] = (int)__ldcs((const long long*)p2f_raw + pix);
        else      fq[s] = __ldcs((const int*)p2f_raw + pix);
        const float* bp = bary + (size_t)pix * 3;
        bq[s][0] = __ldcs(bp + 0);
        bq[s][1] = __ldcs(bp + 1);
        bq[s][2] = __ldcs(bp + 2);
    };

    // issue 3 x LDG.256 gather (96 B face payload) for slot s into buffer buf
    auto load_attr = [&](int buf, int s) {
        int f = fq[s];
        if (f >= 0) {
            const float* a = attr + (size_t)f * 24;
            ldg256_el(a + 0,  A[buf][0], A[buf][1]);   // vertex 0: ch 0-7
            ldg256_el(a + 8,  A[buf][2], A[buf][3]);   // vertex 1
            ldg256_el(a + 16, A[buf][4], A[buf][5]);   // vertex 2
        }
    };

    // ---- prologue: fill the pipe ----
    load_idx(0, 0);
    load_idx(1, 1);
    load_attr(0, 0);

    #pragma unroll
    for (int j = 0; j < ITERS; j++) {
        if (j + 2 < ITERS) load_idx((j + 2) % 3, j + 2);
        if (j + 1 < ITERS) load_attr((j + 1) & 1, (j + 1) % 3);

        // ---- compute + store stage j ----
        const int s   = j % 3;
        const int buf = j & 1;
        const int f   = fq[s];
        float o[DD], vis;
        if (f >= 0) {
            float b0 = bq[s][0], b1 = bq[s][1], b2 = bq[s][2];
            float4 A0 = A[buf][0], A1 = A[buf][1];
            float4 A2 = A[buf][2], A3 = A[buf][3];
            float4 A4 = A[buf][4], A5 = A[buf][5];
            o[0] = b0 * A0.x + b1 * A2.x + b2 * A4.x;
            o[1] = b0 * A0.y + b1 * A2.y + b2 * A4.y;
            o[2] = b0 * A0.z + b1 * A2.z + b2 * A4.z;
            o[3] = b0 * A0.w + b1 * A2.w + b2 * A4.w;
            o[4] = b0 * A1.x + b1 * A3.x + b2 * A5.x;
            o[5] = b0 * A1.y + b1 * A3.y + b2 * A5.y;
            o[6] = b0 * A1.z + b1 * A3.z + b2 * A5.z;
            o[7] = b0 * A1.w + b1 * A3.w + b2 * A5.w;
            vis = 1.0f;
        } else {
            #pragma unroll
            for (int d = 0; d < DD; d++) o[d] = 0.0f;
            vis = 0.0f;
        }

        // output [N][9][H][W]: warp-coalesced plane-major stores, evict-first
        int pix = t + j * TOTAL;
        int n   = pix >> 18;             // / HWC (2^18)
        int hw  = pix & (HWC - 1);
        float* ob = out + (size_t)n * (DD + 1) * HWC + hw;
        #pragma unroll
        for (int d = 0; d < DD; d++)
            __stcs(ob + (size_t)d * HWC, o[d]);
        __stcs(ob + (size_t)DD * HWC, vis);
    }
}

extern "C" void kernel_launch(void* const* d_in, const int* in_sizes, int n_in,
                              void* d_out, int out_size) {
    const void*  p2f  = d_in[0];                    // [N,H,W,1] int32 or int64
    const float* bary = (const float*)d_in[1];      // [N,H,W,1,3] fp32
    const float* attr = (const float*)d_in[2];      // [N,NF,3,8] fp32
    float*       out  = (float*)d_out;              // [N,9,H,W] fp32

    interp_kernel<<<GRID, TPB>>>(p2f, bary, attr, out);
}

// round 11
// speedup vs baseline: 1.3109x; 1.0593x over previous
#include <cuda_runtime.h>
#include <cstdint>

// Problem constants (fixed by reference)
#define NB    8
#define HH    512
#define WW    512
#define DD    8
#define HWC   (HH * WW)          // 262144
#define NPIX  (NB * HWC)         // 2097152 = 2^21
#define TPB   128
#define NSM   148
#define BPSM  6                  // blocks resident per SM (80 regs x 128 thr)
#define GRID  (NSM * BPSM * 2)   // 1776 = exactly 2 full waves
#define TOTAL (GRID * TPB)       // 227328 threads
#define MAXJ  ((NPIX + TOTAL - 1) / TOTAL)   // 10 (last stage partial)

// 256-bit gather load with L2 evict_last (sm_103 requires v8.b32 for this hint).
__device__ __forceinline__ void ldg256_el(const void* p, float4& a, float4& b) {
    asm volatile(
        "ld.global.nc.L2::evict_last.v8.b32 {%0,%1,%2,%3,%4,%5,%6,%7}, [%8];"
        : "=r"(*(unsigned*)&a.x), "=r"(*(unsigned*)&a.y),
          "=r"(*(unsigned*)&a.z), "=r"(*(unsigned*)&a.w),
          "=r"(*(unsigned*)&b.x), "=r"(*(unsigned*)&b.y),
          "=r"(*(unsigned*)&b.z), "=r"(*(unsigned*)&b.w)
        : "l"(p));
}

__global__ __launch_bounds__(TPB, BPSM)
void interp_kernel(const void* __restrict__ p2f_raw,
                   const float* __restrict__ bary,     // [NPIX,3]
                   const float* __restrict__ attr,     // [N*NF][3][8] fp32 = 96 B/face
                   float* __restrict__ out)            // [N][9][H][W]
{
    const int t = blockIdx.x * TPB + threadIdx.x;      // t < 227328

    // ---- dtype detection (int64 vs int32 pix_to_face), warp-uniform ----
    // t < NPIX/2, so word index 2t+1 is in-bounds under BOTH interpretations.
    // int64: hi word of every element is 0 or 0xFFFFFFFF -> 32/32 lanes match.
    // int32: sampled words are arbitrary face values -> ~6-7/32 match.
    const unsigned int* pw = (const unsigned int*)p2f_raw;
    unsigned int hiw = __ldg(&pw[2 * t + 1]);
    bool m = (hiw == 0u) || (hiw == 0xFFFFFFFFu);
    const bool is64 = __popc(__ballot_sync(0xffffffffu, m)) >= 28;

    // Pipeline state: 3 idx/bary slots, 2 attr buffers.
    int    fq[3];
    float  bq[3][3];
    float4 A[2][6];

    // issue face index + barycentrics for stage j into slot s (single-use -> streaming)
    auto load_idx = [&](int s, int j) {
        int pix = t + j * TOTAL;
        if (pix < NPIX) {
            if (is64) fq[s] = (int)__ldcs((const long long*)p2f_raw + pix);
            else      fq[s] = __ldcs((const int*)p2f_raw + pix);
            const float* bp = bary + (size_t)pix * 3;
            bq[s][0] = __ldcs(bp + 0);
            bq[s][1] = __ldcs(bp + 1);
            bq[s][2] = __ldcs(bp + 2);
        } else {
            fq[s] = -1;                       // makes load_attr/compute skip
        }
    };

    // issue 3 x LDG.256 gather (96 B face payload) for slot s into buffer buf
    auto load_attr = [&](int buf, int s) {
        int f = fq[s];
        if (f >= 0) {
            const float* a = attr + (size_t)f * 24;
            ldg256_el(a + 0,  A[buf][0], A[buf][1]);   // vertex 0: ch 0-7
            ldg256_el(a + 8,  A[buf][2], A[buf][3]);   // vertex 1
            ldg256_el(a + 16, A[buf][4], A[buf][5]);   // vertex 2
        }
    };

    // ---- prologue: fill the pipe ----
    load_idx(0, 0);
    load_idx(1, 1);
    load_attr(0, 0);

    #pragma unroll
    for (int j = 0; j < MAXJ; j++) {
        if (j + 2 < MAXJ) load_idx((j + 2) % 3, j + 2);
        if (j + 1 < MAXJ) load_attr((j + 1) & 1, (j + 1) % 3);

        // ---- compute + store stage j ----
        int pix = t + j * TOTAL;
        if (pix >= NPIX) break;               // only possible at j == MAXJ-1

        const int s   = j % 3;
        const int buf = j & 1;
        const int f   = fq[s];
        float o[DD], vis;
        if (f >= 0) {
            float b0 = bq[s][0], b1 = bq[s][1], b2 = bq[s][2];
            float4 A0 = A[buf][0], A1 = A[buf][1];
            float4 A2 = A[buf][2], A3 = A[buf][3];
            float4 A4 = A[buf][4], A5 = A[buf][5];
            o[0] = b0 * A0.x + b1 * A2.x + b2 * A4.x;
            o[1] = b0 * A0.y + b1 * A2.y + b2 * A4.y;
            o[2] = b0 * A0.z + b1 * A2.z + b2 * A4.z;
            o[3] = b0 * A0.w + b1 * A2.w + b2 * A4.w;
            o[4] = b0 * A1.x + b1 * A3.x + b2 * A5.x;
            o[5] = b0 * A1.y + b1 * A3.y + b2 * A5.y;
            o[6] = b0 * A1.z + b1 * A3.z + b2 * A5.z;
            o[7] = b0 * A1.w + b1 * A3.w + b2 * A5.w;
            vis = 1.0f;
        } else {
            #pragma unroll
            for (int d = 0; d < DD; d++) o[d] = 0.0f;
            vis = 0.0f;
        }

        // output [N][9][H][W]: warp-coalesced plane-major stores, streaming
        int n  = pix >> 18;             // / HWC (2^18)
        int hw = pix & (HWC - 1);
        float* ob = out + (size_t)n * (DD + 1) * HWC + hw;
        #pragma unroll
        for (int d = 0; d < DD; d++)
            __stcs(ob + (size_t)d * HWC, o[d]);
        __stcs(ob + (size_t)DD * HWC, vis);
    }
}

extern "C" void kernel_launch(void* const* d_in, const int* in_sizes, int n_in,
                              void* d_out, int out_size) {
    const void*  p2f  = d_in[0];                    // [N,H,W,1] int32 or int64
    const float* bary = (const float*)d_in[1];      // [N,H,W,1,3] fp32
    const float* attr = (const float*)d_in[2];      // [N,NF,3,8] fp32
    float*       out  = (float*)d_out;              // [N,9,H,W] fp32

    interp_kernel<<<GRID, TPB>>>(p2f, bary, attr, out);
}

// round 12
// speedup vs baseline: 1.3571x; 1.0353x over previous
#include <cuda_runtime.h>
#include <cstdint>

// Problem constants (fixed by reference)
#define NB    8
#define HH    512
#define WW    512
#define DD    8
#define HWC   (HH * WW)          // 262144
#define NPIX  (NB * HWC)         // 2097152 = 2^21
#define TPB   128
#define NSM   148
#define BPSM  6                  // blocks resident per SM (80 regs x 128 thr)
#define GRID  (NSM * BPSM)       // 888 = exactly ONE full wave (persistent)
#define TOTAL (GRID * TPB)       // 113664 threads
#define MAXJ  ((NPIX + TOTAL - 1) / TOTAL)   // 19 (last stage partial)

// 256-bit gather load with L2 evict_last (sm_103 requires v8.b32 for this hint).
__device__ __forceinline__ void ldg256_el(const void* p, float4& a, float4& b) {
    asm volatile(
        "ld.global.nc.L2::evict_last.v8.b32 {%0,%1,%2,%3,%4,%5,%6,%7}, [%8];"
        : "=r"(*(unsigned*)&a.x), "=r"(*(unsigned*)&a.y),
          "=r"(*(unsigned*)&a.z), "=r"(*(unsigned*)&a.w),
          "=r"(*(unsigned*)&b.x), "=r"(*(unsigned*)&b.y),
          "=r"(*(unsigned*)&b.z), "=r"(*(unsigned*)&b.w)
        : "l"(p));
}

__global__ __launch_bounds__(TPB, BPSM)
void interp_kernel(const void* __restrict__ p2f_raw,
                   const float* __restrict__ bary,     // [NPIX,3]
                   const float* __restrict__ attr,     // [N*NF][3][8] fp32 = 96 B/face
                   float* __restrict__ out)            // [N][9][H][W]
{
    const int t = blockIdx.x * TPB + threadIdx.x;      // t < 113664

    // ---- dtype detection (int64 vs int32 pix_to_face), warp-uniform ----
    // t < NPIX/2, so word index 2t+1 is in-bounds under BOTH interpretations.
    // int64: hi word of every element is 0 or 0xFFFFFFFF -> 32/32 lanes match.
    // int32: sampled words are arbitrary face values -> ~6-7/32 match.
    const unsigned int* pw = (const unsigned int*)p2f_raw;
    unsigned int hiw = __ldg(&pw[2 * t + 1]);
    bool m = (hiw == 0u) || (hiw == 0xFFFFFFFFu);
    const bool is64 = __popc(__ballot_sync(0xffffffffu, m)) >= 28;

    // Pipeline state: 3 idx/bary slots, 2 attr buffers.
    int    fq[3];
    float  bq[3][3];
    float4 A[2][6];

    // issue face index + barycentrics for stage j into slot s (single-use -> streaming)
    auto load_idx = [&](int s, int j) {
        int pix = t + j * TOTAL;
        if (pix < NPIX) {
            if (is64) fq[s] = (int)__ldcs((const long long*)p2f_raw + pix);
            else      fq[s] = __ldcs((const int*)p2f_raw + pix);
            const float* bp = bary + (size_t)pix * 3;
            bq[s][0] = __ldcs(bp + 0);
            bq[s][1] = __ldcs(bp + 1);
            bq[s][2] = __ldcs(bp + 2);
        } else {
            fq[s] = -1;                       // makes load_attr/compute skip
        }
    };

    // issue 3 x LDG.256 gather (96 B face payload) for slot s into buffer buf
    auto load_attr = [&](int buf, int s) {
        int f = fq[s];
        if (f >= 0) {
            const float* a = attr + (size_t)f * 24;
            ldg256_el(a + 0,  A[buf][0], A[buf][1]);   // vertex 0: ch 0-7
            ldg256_el(a + 8,  A[buf][2], A[buf][3]);   // vertex 1
            ldg256_el(a + 16, A[buf][4], A[buf][5]);   // vertex 2
        }
    };

    // ---- prologue: fill the pipe ----
    load_idx(0, 0);
    load_idx(1, 1);
    load_attr(0, 0);

    #pragma unroll
    for (int j = 0; j < MAXJ; j++) {
        if (j + 2 < MAXJ) load_idx((j + 2) % 3, j + 2);
        if (j + 1 < MAXJ) load_attr((j + 1) & 1, (j + 1) % 3);

        // ---- compute + store stage j ----
        int pix = t + j * TOTAL;
        if (pix >= NPIX) break;               // only possible at j == MAXJ-1

        const int s   = j % 3;
        const int buf = j & 1;
        const int f   = fq[s];
        float o[DD], vis;
        if (f >= 0) {
            float b0 = bq[s][0], b1 = bq[s][1], b2 = bq[s][2];
            float4 A0 = A[buf][0], A1 = A[buf][1];
            float4 A2 = A[buf][2], A3 = A[buf][3];
            float4 A4 = A[buf][4], A5 = A[buf][5];
            o[0] = b0 * A0.x + b1 * A2.x + b2 * A4.x;
            o[1] = b0 * A0.y + b1 * A2.y + b2 * A4.y;
            o[2] = b0 * A0.z + b1 * A2.z + b2 * A4.z;
            o[3] = b0 * A0.w + b1 * A2.w + b2 * A4.w;
            o[4] = b0 * A1.x + b1 * A3.x + b2 * A5.x;
            o[5] = b0 * A1.y + b1 * A3.y + b2 * A5.y;
            o[6] = b0 * A1.z + b1 * A3.z + b2 * A5.z;
            o[7] = b0 * A1.w + b1 * A3.w + b2 * A5.w;
            vis = 1.0f;
        } else {
            #pragma unroll
            for (int d = 0; d < DD; d++) o[d] = 0.0f;
            vis = 0.0f;
        }

        // output [N][9][H][W]: warp-coalesced plane-major stores, streaming
        int n  = pix >> 18;             // / HWC (2^18)
        int hw = pix & (HWC - 1);
        float* ob = out + (size_t)n * (DD + 1) * HWC + hw;
        #pragma unroll
        for (int d = 0; d < DD; d++)
            __stcs(ob + (size_t)d * HWC, o[d]);
        __stcs(ob + (size_t)DD * HWC, vis);
    }
}

extern "C" void kernel_launch(void* const* d_in, const int* in_sizes, int n_in,
                              void* d_out, int out_size) {
    const void*  p2f  = d_in[0];                    // [N,H,W,1] int32 or int64
    const float* bary = (const float*)d_in[1];      // [N,H,W,1,3] fp32
    const float* attr = (const float*)d_in[2];      // [N,NF,3,8] fp32
    float*       out  = (float*)d_out;              // [N,9,H,W] fp32

    interp_kernel<<<GRID, TPB>>>(p2f, bary, attr, out);
}